// round 7
// baseline (speedup 1.0000x reference)
#include <cuda_runtime.h>
#include <cuda_fp16.h>
#include <cstdint>

// ---------------------------------------------------------------------------
// SwinStyleAttention, fp16 mma.sync path (fp32 accumulate everywhere).
// B=8, C=128, H=W=256, WS=8, SS=4, HEADS=4, DH=32.
// One CTA = 2 horizontally adjacent windows = 128 tokens. 4096 CTAs, 256 thr.
// ---------------------------------------------------------------------------

#define SCALE_F 0.17677669529663687f

// smem byte offsets (fp16 tiles: 128 rows x 128 cols = 32 KB, 256 B/row)
#define X_OFF   0          // X -> P scratch (warps 0-3)
#define Q_OFF   32768      // Q
#define K_OFF   65536      // K -> O
#define V_OFF   98304      // V -> Y (fp32, stride 130, spills into W0/W1 tail)
#define W0_OFF  131072     // Wq -> Wv -> P scratch (warps 4-7)
#define W1_OFF  163840     // Wk -> Wproj
#define Y_OFF   V_OFF
#define SMEM_TOTAL 196608

__device__ __align__(16) __half g_wh[4][16384];   // WqT, WkT, WvT, WprojT

// ---------------------------------------------------------------------------
__device__ __forceinline__ uint32_t s2u(const void* p) {
    uint32_t a;
    asm("{ .reg .u64 t; cvta.to.shared.u64 t, %1; cvt.u32.u64 %0, t; }" : "=r"(a) : "l"(p));
    return a;
}
// byte offset of (row, 16B-chunk) in a 256B-row tile, XOR-swizzled
__device__ __forceinline__ uint32_t xoff(int row, int chunk) {
    return (uint32_t)(row * 256 + ((chunk ^ (row & 7)) << 4));
}
// same for the 128B-row P tile
__device__ __forceinline__ uint32_t poff(int row, int chunk) {
    return (uint32_t)(row * 128 + ((chunk ^ (row & 7)) << 4));
}

__device__ __forceinline__ void ldm4(uint32_t r[4], uint32_t addr) {
    asm volatile("ldmatrix.sync.aligned.m8n8.x4.shared.b16 {%0,%1,%2,%3}, [%4];"
                 : "=r"(r[0]), "=r"(r[1]), "=r"(r[2]), "=r"(r[3]) : "r"(addr));
}
__device__ __forceinline__ void ldm4t(uint32_t r[4], uint32_t addr) {
    asm volatile("ldmatrix.sync.aligned.m8n8.x4.trans.shared.b16 {%0,%1,%2,%3}, [%4];"
                 : "=r"(r[0]), "=r"(r[1]), "=r"(r[2]), "=r"(r[3]) : "r"(addr));
}
__device__ __forceinline__ void mmaf16(float c[4], const uint32_t a[4],
                                       uint32_t b0, uint32_t b1) {
    asm volatile(
        "mma.sync.aligned.m16n8k16.row.col.f32.f16.f16.f32 "
        "{%0,%1,%2,%3},{%4,%5,%6,%7},{%8,%9},{%0,%1,%2,%3};"
        : "+f"(c[0]), "+f"(c[1]), "+f"(c[2]), "+f"(c[3])
        : "r"(a[0]), "r"(a[1]), "r"(a[2]), "r"(a[3]), "r"(b0), "r"(b1));
}

__device__ __forceinline__ void cp16(uint32_t dst, const void* src) {
    asm volatile("cp.async.cg.shared.global [%0], [%1], 16;" :: "r"(dst), "l"(src));
}
#define CP_COMMIT() asm volatile("cp.async.commit_group;" ::: "memory")
#define CP_WAIT1()  asm volatile("cp.async.wait_group 1;" ::: "memory")
#define CP_WAIT0()  asm volatile("cp.async.wait_group 0;" ::: "memory")

// stage a [128 n][128 k] fp16 transposed weight into the swizzled tile
__device__ __forceinline__ void stageW(uint32_t dstBase, const __half* src, int tid) {
#pragma unroll
    for (int i = 0; i < 8; i++) {
        int id = i * 256 + tid;          // 0..2047
        int n = id >> 4, ch = id & 15;
        cp16(dstBase + xoff(n, ch), src + n * 128 + ch * 8);
    }
    CP_COMMIT();
}

// ---------------------------------------------------------------------------
__global__ void prep_kernel(const float* __restrict__ wqkv,
                            const float* __restrict__ wproj) {
    int i = blockIdx.x * blockDim.x + threadIdx.x;   // 0..65535
    int m = i >> 14, n = (i >> 7) & 127, k = i & 127;
    float v = (m < 3) ? wqkv[k * 384 + m * 128 + n] : wproj[k * 128 + n];
    g_wh[m][n * 128 + k] = __float2half_rn(v);
}

// ---------------------------------------------------------------------------
// D[128,128] = A[128,128] @ B[128,128]; 8 warps, warp tile 32(M) x 64(N).
// EPI: 0 = scale+fp16 (Q), 1 = fp16 (K), 2 = fp16 (V), 3 = fp32+bias -> Y.
template <int EPI>
__device__ __forceinline__ void gemm128(uint32_t sb, char* smem, int aOff, int bOff,
                                        int dOff, const float* __restrict__ bias) {
    const int lane = threadIdx.x & 31, wid = threadIdx.x >> 5;
    const int g = lane >> 2, tg = lane & 3;
    const int lg = lane >> 3, lr = lane & 7;
    const int m0 = (wid >> 1) * 32, n0 = (wid & 1) * 64;

    float acc[2][8][4];
#pragma unroll
    for (int mi = 0; mi < 2; mi++)
#pragma unroll
        for (int nb = 0; nb < 8; nb++)
#pragma unroll
            for (int j = 0; j < 4; j++) acc[mi][nb][j] = 0.f;

#pragma unroll
    for (int ks = 0; ks < 8; ks++) {
        uint32_t a[2][4];
#pragma unroll
        for (int mi = 0; mi < 2; mi++) {
            int row = m0 + mi * 16 + (lg & 1) * 8 + lr;
            ldm4(a[mi], sb + aOff + xoff(row, ks * 2 + (lg >> 1)));
        }
#pragma unroll
        for (int ni = 0; ni < 4; ni++) {
            uint32_t bf[4];
            int row = n0 + ni * 16 + (lg >> 1) * 8 + lr;
            ldm4(bf, sb + bOff + xoff(row, ks * 2 + (lg & 1)));
#pragma unroll
            for (int mi = 0; mi < 2; mi++) {
                mmaf16(acc[mi][2 * ni], a[mi], bf[0], bf[1]);
                mmaf16(acc[mi][2 * ni + 1], a[mi], bf[2], bf[3]);
            }
        }
    }

    if (EPI == 3) __syncthreads();   // protect Y overlay of V/W0/W1 + O reads

#pragma unroll
    for (int mi = 0; mi < 2; mi++)
#pragma unroll
        for (int nb = 0; nb < 8; nb++) {
            int r = m0 + mi * 16 + g;
            int c = n0 + nb * 8 + 2 * tg;
            float v0 = acc[mi][nb][0], v1 = acc[mi][nb][1];
            float v2 = acc[mi][nb][2], v3 = acc[mi][nb][3];
            if (EPI == 0) { v0 *= SCALE_F; v1 *= SCALE_F; v2 *= SCALE_F; v3 *= SCALE_F; }
            if (EPI < 3) {
                *(__half2*)(smem + dOff + xoff(r, c >> 3) + (c & 7) * 2) =
                    __floats2half2_rn(v0, v1);
                *(__half2*)(smem + dOff + xoff(r + 8, c >> 3) + (c & 7) * 2) =
                    __floats2half2_rn(v2, v3);
            } else {
                float b0 = __ldg(bias + c), b1 = __ldg(bias + c + 1);
                float* Y = (float*)(smem + dOff);
                Y[r * 130 + c] = v0 + b0;
                Y[r * 130 + c + 1] = v1 + b1;
                Y[(r + 8) * 130 + c] = v2 + b0;
                Y[(r + 8) * 130 + c + 1] = v3 + b1;
            }
        }
}

// ---------------------------------------------------------------------------
__global__ void __launch_bounds__(256, 1)
swin_kernel(const float* __restrict__ x,
            const float* __restrict__ bproj,
            float* __restrict__ out) {
    extern __shared__ char smem[];
    const uint32_t sb = s2u(smem);
    const int tid = threadIdx.x, wid = tid >> 5, lane = tid & 31;
    const int g = lane >> 2, tg = lane & 3;
    const int lg = lane >> 3, lr = lane & 7;

    const int p = blockIdx.x;
    const int b = p >> 9, rm = p & 511;
    const int hs0 = (rm >> 4) * 8 + 4;      // +SS cyclic shift
    const int ws0 = (rm & 15) * 16 + 4;
    const float* xb = x + (size_t)b * (128 * 256 * 256);

    // ---- stage Wq, Wk; gather shifted X (fp16) -----------------------------
    stageW(sb + W0_OFF, g_wh[0], tid);
    stageW(sb + W1_OFF, g_wh[1], tid);
#pragma unroll 4
    for (int i = 0; i < 32; i++) {
        int idx = i * 256 + tid;            // 8192 channel-pair x token
        int c2 = idx >> 7, t = idx & 127;
        int r = (t >> 3) & 7, s16 = ((t >> 6) << 3) | (t & 7);
        int h = (hs0 + r) & 255, wv = (ws0 + s16) & 255;
        const float* src = xb + (size_t)(2 * c2) * 65536 + h * 256 + wv;
        float v0 = __ldg(src), v1 = __ldg(src + 65536);
        *(__half2*)(smem + X_OFF + xoff(t, c2 >> 2) + (c2 & 3) * 4) =
            __floats2half2_rn(v0, v1);
    }
    CP_WAIT0();
    __syncthreads();

    // ---- QKV projections (weights double-buffered via cp.async) ------------
    gemm128<0>(sb, smem, X_OFF, W0_OFF, Q_OFF, nullptr);   // Q (scaled)
    __syncthreads();                                       // Wq reads done
    stageW(sb + W0_OFF, g_wh[2], tid);                     // Wv -> W0
    gemm128<1>(sb, smem, X_OFF, W1_OFF, K_OFF, nullptr);   // K
    __syncthreads();                                       // Wk reads done
    stageW(sb + W1_OFF, g_wh[3], tid);                     // Wproj -> W1
    CP_WAIT1();                                            // Wv arrived
    __syncthreads();
    gemm128<2>(sb, smem, X_OFF, W0_OFF, V_OFF, nullptr);   // V
    __syncthreads();                                       // V visible; X, W0 free

    // ---- attention: warp = (window, head); 64x64 S, softmax, PV ------------
    {
        const int w = wid >> 2, hd = wid & 3;
        const int tb0 = w * 64;
        const int pO = (wid < 4) ? (X_OFF + wid * 8192) : (W0_OFF + (wid - 4) * 8192);

#pragma unroll 1
        for (int mi = 0; mi < 4; mi++) {
            float s[8][4];
#pragma unroll
            for (int nb = 0; nb < 8; nb++)
#pragma unroll
                for (int j = 0; j < 4; j++) s[nb][j] = 0.f;
#pragma unroll
            for (int ks = 0; ks < 2; ks++) {
                uint32_t a[4];
                int arow = tb0 + mi * 16 + (lg & 1) * 8 + lr;
                ldm4(a, sb + Q_OFF + xoff(arow, hd * 4 + ks * 2 + (lg >> 1)));
#pragma unroll
                for (int ni = 0; ni < 4; ni++) {
                    uint32_t bf[4];
                    int brow = tb0 + ni * 16 + (lg >> 1) * 8 + lr;
                    ldm4(bf, sb + K_OFF + xoff(brow, hd * 4 + ks * 2 + (lg & 1)));
                    mmaf16(s[2 * ni], a, bf[0], bf[1]);
                    mmaf16(s[2 * ni + 1], a, bf[2], bf[3]);
                }
            }
            // softmax on the two 8-row halves this thread touches
#pragma unroll
            for (int hf = 0; hf < 2; hf++) {
                float m = -3.0e38f;
#pragma unroll
                for (int nb = 0; nb < 8; nb++)
                    m = fmaxf(m, fmaxf(s[nb][2 * hf], s[nb][2 * hf + 1]));
                m = fmaxf(m, __shfl_xor_sync(0xffffffffu, m, 1));
                m = fmaxf(m, __shfl_xor_sync(0xffffffffu, m, 2));
                float e[16], sum = 0.f;
#pragma unroll
                for (int nb = 0; nb < 8; nb++) {
                    float e0 = __expf(s[nb][2 * hf] - m);
                    float e1 = __expf(s[nb][2 * hf + 1] - m);
                    e[2 * nb] = e0; e[2 * nb + 1] = e1; sum += e0 + e1;
                }
                sum += __shfl_xor_sync(0xffffffffu, sum, 1);
                sum += __shfl_xor_sync(0xffffffffu, sum, 2);
                float inv = 1.f / sum;
                int r = mi * 16 + hf * 8 + g;
#pragma unroll
                for (int nb = 0; nb < 8; nb++) {
                    int c = nb * 8 + 2 * tg;
                    *(__half2*)(smem + pO + poff(r, c >> 3) + (c & 7) * 2) =
                        __floats2half2_rn(e[2 * nb] * inv, e[2 * nb + 1] * inv);
                }
            }
        }
        __syncwarp();

        // O = P @ V_head -> overwrite own K slot
#pragma unroll 1
        for (int mi = 0; mi < 4; mi++) {
            float o[4][4];
#pragma unroll
            for (int nb = 0; nb < 4; nb++)
#pragma unroll
                for (int j = 0; j < 4; j++) o[nb][j] = 0.f;
#pragma unroll
            for (int tk = 0; tk < 4; tk++) {
                uint32_t a[4];
                int arow = mi * 16 + (lg & 1) * 8 + lr;
                ldm4(a, sb + pO + poff(arow, tk * 2 + (lg >> 1)));
#pragma unroll
                for (int dp = 0; dp < 2; dp++) {
                    uint32_t bf[4];
                    int brow = tb0 + tk * 16 + (lg & 1) * 8 + lr;
                    ldm4t(bf, sb + V_OFF + xoff(brow, hd * 4 + dp * 2 + (lg >> 1)));
                    mmaf16(o[2 * dp], a, bf[0], bf[1]);
                    mmaf16(o[2 * dp + 1], a, bf[2], bf[3]);
                }
            }
#pragma unroll
            for (int nb = 0; nb < 4; nb++) {
                int r = tb0 + mi * 16 + g;
                int c = hd * 32 + nb * 8 + 2 * tg;
                *(__half2*)(smem + K_OFF + xoff(r, c >> 3) + (c & 7) * 2) =
                    __floats2half2_rn(o[nb][0], o[nb][1]);
                *(__half2*)(smem + K_OFF + xoff(r + 8, c >> 3) + (c & 7) * 2) =
                    __floats2half2_rn(o[nb][2], o[nb][3]);
            }
        }
    }
    __syncthreads();       // all O visible
    CP_WAIT0();            // Wproj arrived

    // ---- Y = O @ WprojT + bias (fp32, into V/W0 region, stride 130) --------
    gemm128<3>(sb, smem, K_OFF, W1_OFF, Y_OFF, bproj);
    __syncthreads();

    // ---- reverse-shift scatter, channels-first -----------------------------
    const float* Y = (const float*)(smem + Y_OFF);
#pragma unroll 4
    for (int i = 0; i < 64; i++) {
        int idx = i * 256 + tid;            // 16384 (c, t)
        int c = idx >> 7, t = idx & 127;
        int r = (t >> 3) & 7, s16 = ((t >> 6) << 3) | (t & 7);
        int h = (hs0 + r) & 255, wv = (ws0 + s16) & 255;
        out[(((size_t)b * 128 + c) * 256 + h) * 256 + wv] = Y[t * 130 + c];
    }
}

extern "C" void kernel_launch(void* const* d_in, const int* in_sizes, int n_in,
                              void* d_out, int out_size) {
    const float* x     = (const float*)d_in[0];
    const float* wqkv  = (const float*)d_in[1];
    const float* wproj = (const float*)d_in[2];
    const float* bproj = (const float*)d_in[3];
    float* out = (float*)d_out;

    prep_kernel<<<256, 256>>>(wqkv, wproj);

    cudaFuncSetAttribute(swin_kernel,
                         cudaFuncAttributeMaxDynamicSharedMemorySize, SMEM_TOTAL);
    swin_kernel<<<4096, 256, SMEM_TOTAL>>>(x, bproj, out);
}

// round 8
// speedup vs baseline: 1.1270x; 1.1270x over previous
#include <cuda_runtime.h>
#include <cuda_fp16.h>
#include <cstdint>

// ---------------------------------------------------------------------------
// SwinStyleAttention, fp16 mma.sync path (fp32 accumulate everywhere).
// B=8, C=128, H=W=256, WS=8, SS=4, HEADS=4, DH=32.
// One CTA = 2 adjacent windows = 128 tokens. 4096 CTAs, 512 threads (16 warps).
// ---------------------------------------------------------------------------

#define SCALE_F 0.17677669529663687f

// smem byte offsets (fp16 tiles: 128 rows x 128 cols = 32 KB, 256 B/row)
#define X_OFF   0          // X -> P scratch (warps 0-7)
#define Q_OFF   32768      // Q
#define K_OFF   65536      // K -> O
#define V_OFF   98304      // V -> Y (fp32, stride 130, spills into W0/W1 head)
#define W0_OFF  131072     // Wq -> Wv -> P scratch (warps 8-15)
#define W1_OFF  163840     // Wk -> Wproj
#define Y_OFF   V_OFF
#define SMEM_TOTAL 196608

__device__ __align__(16) __half g_wh[4][16384];   // WqT, WkT, WvT, WprojT

// ---------------------------------------------------------------------------
__device__ __forceinline__ uint32_t s2u(const void* p) {
    uint32_t a;
    asm("{ .reg .u64 t; cvta.to.shared.u64 t, %1; cvt.u32.u64 %0, t; }" : "=r"(a) : "l"(p));
    return a;
}
// byte offset of (row, 16B-chunk) in a 256B-row tile, XOR-swizzled
__device__ __forceinline__ uint32_t xoff(int row, int chunk) {
    return (uint32_t)(row * 256 + ((chunk ^ (row & 7)) << 4));
}
// same for the 128B-row P tile
__device__ __forceinline__ uint32_t poff(int row, int chunk) {
    return (uint32_t)(row * 128 + ((chunk ^ (row & 7)) << 4));
}

__device__ __forceinline__ void ldm4(uint32_t r[4], uint32_t addr) {
    asm volatile("ldmatrix.sync.aligned.m8n8.x4.shared.b16 {%0,%1,%2,%3}, [%4];"
                 : "=r"(r[0]), "=r"(r[1]), "=r"(r[2]), "=r"(r[3]) : "r"(addr));
}
__device__ __forceinline__ void ldm4t(uint32_t r[4], uint32_t addr) {
    asm volatile("ldmatrix.sync.aligned.m8n8.x4.trans.shared.b16 {%0,%1,%2,%3}, [%4];"
                 : "=r"(r[0]), "=r"(r[1]), "=r"(r[2]), "=r"(r[3]) : "r"(addr));
}
__device__ __forceinline__ void mmaf16(float c[4], const uint32_t a[4],
                                       uint32_t b0, uint32_t b1) {
    asm volatile(
        "mma.sync.aligned.m16n8k16.row.col.f32.f16.f16.f32 "
        "{%0,%1,%2,%3},{%4,%5,%6,%7},{%8,%9},{%0,%1,%2,%3};"
        : "+f"(c[0]), "+f"(c[1]), "+f"(c[2]), "+f"(c[3])
        : "r"(a[0]), "r"(a[1]), "r"(a[2]), "r"(a[3]), "r"(b0), "r"(b1));
}

__device__ __forceinline__ void cp16(uint32_t dst, const void* src) {
    asm volatile("cp.async.cg.shared.global [%0], [%1], 16;" :: "r"(dst), "l"(src));
}
#define CP_COMMIT() asm volatile("cp.async.commit_group;" ::: "memory")
#define CP_WAIT1()  asm volatile("cp.async.wait_group 1;" ::: "memory")
#define CP_WAIT0()  asm volatile("cp.async.wait_group 0;" ::: "memory")

// stage a [128 n][128 k] fp16 transposed weight into the swizzled tile
__device__ __forceinline__ void stageW(uint32_t dstBase, const __half* src, int tid) {
#pragma unroll
    for (int i = 0; i < 4; i++) {
        int id = i * 512 + tid;          // 0..2047
        int n = id >> 4, ch = id & 15;
        cp16(dstBase + xoff(n, ch), src + n * 128 + ch * 8);
    }
    CP_COMMIT();
}

// ---------------------------------------------------------------------------
__global__ void prep_kernel(const float* __restrict__ wqkv,
                            const float* __restrict__ wproj) {
    int i = blockIdx.x * blockDim.x + threadIdx.x;   // 0..65535
    int m = i >> 14, n = (i >> 7) & 127, k = i & 127;
    float v = (m < 3) ? wqkv[k * 384 + m * 128 + n] : wproj[k * 128 + n];
    g_wh[m][n * 128 + k] = __float2half_rn(v);
}

// ---------------------------------------------------------------------------
// D[128,128] = A[128,128] @ B[128,128]; 16 warps, warp tile 32(M) x 32(N).
// EPI: 0 = scale+fp16 (Q), 1 = fp16 (K), 2 = fp16 (V), 3 = fp32+bias -> Y.
template <int EPI>
__device__ __forceinline__ void gemm128(uint32_t sb, char* smem, int aOff, int bOff,
                                        int dOff, const float* __restrict__ bias) {
    const int lane = threadIdx.x & 31, wid = threadIdx.x >> 5;
    const int g = lane >> 2, tg = lane & 3;
    const int lg = lane >> 3, lr = lane & 7;
    const int m0 = (wid >> 2) * 32, n0 = (wid & 3) * 32;

    float acc[2][4][4];
#pragma unroll
    for (int mi = 0; mi < 2; mi++)
#pragma unroll
        for (int nb = 0; nb < 4; nb++)
#pragma unroll
            for (int j = 0; j < 4; j++) acc[mi][nb][j] = 0.f;

#pragma unroll
    for (int ks = 0; ks < 8; ks++) {
        uint32_t a[2][4];
#pragma unroll
        for (int mi = 0; mi < 2; mi++)
            ldm4(a[mi], sb + aOff + xoff(m0 + mi * 16 + (lg & 1) * 8 + lr,
                                         ks * 2 + (lg >> 1)));
#pragma unroll
        for (int ni = 0; ni < 2; ni++) {
            uint32_t bf[4];
            ldm4(bf, sb + bOff + xoff(n0 + ni * 16 + (lg >> 1) * 8 + lr,
                                      ks * 2 + (lg & 1)));
#pragma unroll
            for (int mi = 0; mi < 2; mi++) {
                mmaf16(acc[mi][2 * ni], a[mi], bf[0], bf[1]);
                mmaf16(acc[mi][2 * ni + 1], a[mi], bf[2], bf[3]);
            }
        }
    }

    if (EPI == 3) __syncthreads();   // protect Y overlay of V/W0/W1 + O reads

#pragma unroll
    for (int mi = 0; mi < 2; mi++)
#pragma unroll
        for (int nb = 0; nb < 4; nb++) {
            int r = m0 + mi * 16 + g;
            int c = n0 + nb * 8 + 2 * tg;
            float v0 = acc[mi][nb][0], v1 = acc[mi][nb][1];
            float v2 = acc[mi][nb][2], v3 = acc[mi][nb][3];
            if (EPI == 0) { v0 *= SCALE_F; v1 *= SCALE_F; v2 *= SCALE_F; v3 *= SCALE_F; }
            if (EPI < 3) {
                *(__half2*)(smem + dOff + xoff(r, c >> 3) + (c & 7) * 2) =
                    __floats2half2_rn(v0, v1);
                *(__half2*)(smem + dOff + xoff(r + 8, c >> 3) + (c & 7) * 2) =
                    __floats2half2_rn(v2, v3);
            } else {
                float b0 = __ldg(bias + c), b1 = __ldg(bias + c + 1);
                float* Y = (float*)(smem + dOff);
                Y[r * 130 + c] = v0 + b0;
                Y[r * 130 + c + 1] = v1 + b1;
                Y[(r + 8) * 130 + c] = v2 + b0;
                Y[(r + 8) * 130 + c + 1] = v3 + b1;
            }
        }
}

// ---------------------------------------------------------------------------
__global__ void __launch_bounds__(512, 1)
swin_kernel(const float* __restrict__ x,
            const float* __restrict__ bproj,
            float* __restrict__ out) {
    extern __shared__ char smem[];
    const uint32_t sb = s2u(smem);
    const int tid = threadIdx.x, wid = tid >> 5, lane = tid & 31;
    const int g = lane >> 2, tg = lane & 3;
    const int lg = lane >> 3, lr = lane & 7;

    const int p = blockIdx.x;
    const int b = p >> 9, rm = p & 511;
    const int hs0 = (rm >> 4) * 8 + 4;      // +SS cyclic shift
    const int ws0 = (rm & 15) * 16 + 4;
    const float* xb = x + (size_t)b * (128 * 256 * 256);

    // ---- stage Wq, Wk; gather shifted X (fp16) -----------------------------
    stageW(sb + W0_OFF, g_wh[0], tid);
    stageW(sb + W1_OFF, g_wh[1], tid);
#pragma unroll 4
    for (int i = 0; i < 16; i++) {
        int idx = i * 512 + tid;            // 8192 (channel-pair, token)
        int c2 = idx >> 7, t = idx & 127;
        int r = (t >> 3) & 7, s16 = ((t >> 6) << 3) | (t & 7);
        int h = (hs0 + r) & 255, wv = (ws0 + s16) & 255;
        const float* src = xb + (size_t)(2 * c2) * 65536 + h * 256 + wv;
        float v0 = __ldg(src), v1 = __ldg(src + 65536);
        *(__half2*)(smem + X_OFF + xoff(t, c2 >> 2) + (c2 & 3) * 4) =
            __floats2half2_rn(v0, v1);
    }
    CP_WAIT0();
    __syncthreads();

    // ---- QKV projections: Q and K back-to-back (independent, no barrier) ---
    gemm128<0>(sb, smem, X_OFF, W0_OFF, Q_OFF, nullptr);   // Q (scaled)
    gemm128<1>(sb, smem, X_OFF, W1_OFF, K_OFF, nullptr);   // K
    __syncthreads();                                       // Wq/Wk reads done
    stageW(sb + W0_OFF, g_wh[2], tid);                     // Wv -> W0
    stageW(sb + W1_OFF, g_wh[3], tid);                     // Wproj -> W1
    CP_WAIT1();                                            // Wv arrived
    __syncthreads();
    gemm128<2>(sb, smem, X_OFF, W0_OFF, V_OFF, nullptr);   // V
    __syncthreads();                                       // V visible; X, W0 free

    // ---- attention: warp = (window, head, row-half) -------------------------
    {
        const int w = wid >> 3, hd = (wid >> 1) & 3, hf2 = wid & 1;
        const int w64 = w * 64;
        const int rb = w64 + hf2 * 32;          // this warp's 32 query rows
        const int pO = (wid < 8) ? (X_OFF + wid * 4096)
                                 : (W0_OFF + (wid - 8) * 4096);

        // S = Q K^T (64 keys), softmax, P -> own 32x64 buffer
#pragma unroll 1
        for (int mi = 0; mi < 2; mi++) {
            float s[8][4];
#pragma unroll
            for (int nb = 0; nb < 8; nb++)
#pragma unroll
                for (int j = 0; j < 4; j++) s[nb][j] = 0.f;
#pragma unroll
            for (int ks = 0; ks < 2; ks++) {
                uint32_t a[4];
                ldm4(a, sb + Q_OFF + xoff(rb + mi * 16 + (lg & 1) * 8 + lr,
                                          hd * 4 + ks * 2 + (lg >> 1)));
#pragma unroll
                for (int ni = 0; ni < 4; ni++) {
                    uint32_t bf[4];
                    ldm4(bf, sb + K_OFF + xoff(w64 + ni * 16 + (lg >> 1) * 8 + lr,
                                               hd * 4 + ks * 2 + (lg & 1)));
                    mmaf16(s[2 * ni], a, bf[0], bf[1]);
                    mmaf16(s[2 * ni + 1], a, bf[2], bf[3]);
                }
            }
#pragma unroll
            for (int hf = 0; hf < 2; hf++) {
                float m = -3.0e38f;
#pragma unroll
                for (int nb = 0; nb < 8; nb++)
                    m = fmaxf(m, fmaxf(s[nb][2 * hf], s[nb][2 * hf + 1]));
                m = fmaxf(m, __shfl_xor_sync(0xffffffffu, m, 1));
                m = fmaxf(m, __shfl_xor_sync(0xffffffffu, m, 2));
                float e[16], sum = 0.f;
#pragma unroll
                for (int nb = 0; nb < 8; nb++) {
                    float e0 = __expf(s[nb][2 * hf] - m);
                    float e1 = __expf(s[nb][2 * hf + 1] - m);
                    e[2 * nb] = e0; e[2 * nb + 1] = e1; sum += e0 + e1;
                }
                sum += __shfl_xor_sync(0xffffffffu, sum, 1);
                sum += __shfl_xor_sync(0xffffffffu, sum, 2);
                float inv = 1.f / sum;
                int r = mi * 16 + hf * 8 + g;    // P-local row 0..31
#pragma unroll
                for (int nb = 0; nb < 8; nb++) {
                    int c = nb * 8 + 2 * tg;
                    *(__half2*)(smem + pO + poff(r, c >> 3) + (c & 7) * 2) =
                        __floats2half2_rn(e[2 * nb] * inv, e[2 * nb + 1] * inv);
                }
            }
        }
        __syncthreads();   // all K/Q reads done; P visible

        // O = P @ V_head -> overwrite own K slot (rows rb.., cols hd*32..)
#pragma unroll 1
        for (int mi = 0; mi < 2; mi++) {
            float o[4][4];
#pragma unroll
            for (int nb = 0; nb < 4; nb++)
#pragma unroll
                for (int j = 0; j < 4; j++) o[nb][j] = 0.f;
#pragma unroll
            for (int tk = 0; tk < 4; tk++) {
                uint32_t a[4];
                ldm4(a, sb + pO + poff(mi * 16 + (lg & 1) * 8 + lr,
                                       tk * 2 + (lg >> 1)));
#pragma unroll
                for (int dp = 0; dp < 2; dp++) {
                    uint32_t bf[4];
                    ldm4t(bf, sb + V_OFF + xoff(w64 + tk * 16 + (lg & 1) * 8 + lr,
                                                hd * 4 + dp * 2 + (lg >> 1)));
                    mmaf16(o[2 * dp], a, bf[0], bf[1]);
                    mmaf16(o[2 * dp + 1], a, bf[2], bf[3]);
                }
            }
#pragma unroll
            for (int nb = 0; nb < 4; nb++) {
                int r = rb + mi * 16 + g;
                int c = hd * 32 + nb * 8 + 2 * tg;
                *(__half2*)(smem + K_OFF + xoff(r, c >> 3) + (c & 7) * 2) =
                    __floats2half2_rn(o[nb][0], o[nb][1]);
                *(__half2*)(smem + K_OFF + xoff(r + 8, c >> 3) + (c & 7) * 2) =
                    __floats2half2_rn(o[nb][2], o[nb][3]);
            }
        }
    }
    __syncthreads();       // all O visible
    CP_WAIT0();            // Wproj arrived

    // ---- Y = O @ WprojT + bias (fp32, stride 130, over V/W0) ---------------
    gemm128<3>(sb, smem, K_OFF, W1_OFF, Y_OFF, bproj);
    __syncthreads();

    // ---- reverse-shift scatter, channels-first -----------------------------
    const float* Y = (const float*)(smem + Y_OFF);
#pragma unroll 4
    for (int i = 0; i < 32; i++) {
        int idx = i * 512 + tid;            // 16384 (c, t)
        int c = idx >> 7, t = idx & 127;
        int r = (t >> 3) & 7, s16 = ((t >> 6) << 3) | (t & 7);
        int h = (hs0 + r) & 255, wv = (ws0 + s16) & 255;
        out[(((size_t)b * 128 + c) * 256 + h) * 256 + wv] = Y[t * 130 + c];
    }
}

extern "C" void kernel_launch(void* const* d_in, const int* in_sizes, int n_in,
                              void* d_out, int out_size) {
    const float* x     = (const float*)d_in[0];
    const float* wqkv  = (const float*)d_in[1];
    const float* wproj = (const float*)d_in[2];
    const float* bproj = (const float*)d_in[3];
    float* out = (float*)d_out;

    prep_kernel<<<256, 256>>>(wqkv, wproj);

    cudaFuncSetAttribute(swin_kernel,
                         cudaFuncAttributeMaxDynamicSharedMemorySize, SMEM_TOTAL);
    swin_kernel<<<4096, 512, SMEM_TOTAL>>>(x, bproj, out);
}

// round 10
// speedup vs baseline: 1.3000x; 1.1535x over previous
#include <cuda_runtime.h>
#include <cuda_fp16.h>
#include <cstdint>

// ---------------------------------------------------------------------------
// SwinStyleAttention, fp16 mma.sync, fp32 accumulate.
// B=8, C=128, H=W=256, WS=8, SS=4, HEADS=4, DH=32.
// One CTA = 1 window = 64 tokens. 8192 CTAs, 256 threads, 2 CTAs/SM.
// ---------------------------------------------------------------------------

#define SCALE_F 0.17677669529663687f

#define X_OFF   0          // X (64x128 fp16, 16KB) -> P scratch warps 0-3
#define Q_OFF   16384      // Q -> P scratch warps 4-7
#define K_OFF   32768      // K -> O
#define W_OFF   49152      // Wq -> Wv -> Wproj (32KB)
#define WB_OFF  81920      // Wk -> V (32KB; V uses first 16KB)
#define SMEM_TOTAL 114688

__device__ __align__(16) __half g_wh[4][16384];   // WqT, WkT, WvT, WprojT

__device__ __forceinline__ uint32_t s2u(const void* p) {
    uint32_t a;
    asm("{ .reg .u64 t; cvta.to.shared.u64 t, %1; cvt.u32.u64 %0, t; }" : "=r"(a) : "l"(p));
    return a;
}
__device__ __forceinline__ uint32_t xoff(int row, int chunk) {
    return (uint32_t)(row * 256 + ((chunk ^ (row & 7)) << 4));
}
__device__ __forceinline__ uint32_t poff(int row, int chunk) {
    return (uint32_t)(row * 128 + ((chunk ^ (row & 7)) << 4));
}
__device__ __forceinline__ void ldm4(uint32_t r[4], uint32_t addr) {
    asm volatile("ldmatrix.sync.aligned.m8n8.x4.shared.b16 {%0,%1,%2,%3}, [%4];"
                 : "=r"(r[0]), "=r"(r[1]), "=r"(r[2]), "=r"(r[3]) : "r"(addr));
}
__device__ __forceinline__ void ldm4t(uint32_t r[4], uint32_t addr) {
    asm volatile("ldmatrix.sync.aligned.m8n8.x4.trans.shared.b16 {%0,%1,%2,%3}, [%4];"
                 : "=r"(r[0]), "=r"(r[1]), "=r"(r[2]), "=r"(r[3]) : "r"(addr));
}
__device__ __forceinline__ void mmaf16(float c[4], const uint32_t a[4],
                                       uint32_t b0, uint32_t b1) {
    asm volatile(
        "mma.sync.aligned.m16n8k16.row.col.f32.f16.f16.f32 "
        "{%0,%1,%2,%3},{%4,%5,%6,%7},{%8,%9},{%0,%1,%2,%3};"
        : "+f"(c[0]), "+f"(c[1]), "+f"(c[2]), "+f"(c[3])
        : "r"(a[0]), "r"(a[1]), "r"(a[2]), "r"(a[3]), "r"(b0), "r"(b1));
}
__device__ __forceinline__ void cp16(uint32_t dst, const void* src) {
    asm volatile("cp.async.cg.shared.global [%0], [%1], 16;" :: "r"(dst), "l"(src));
}
#define CP_COMMIT() asm volatile("cp.async.commit_group;" ::: "memory")
#define CP_WAIT0()  asm volatile("cp.async.wait_group 0;" ::: "memory")

__device__ __forceinline__ void stageW(uint32_t dstBase, const __half* src, int tid) {
#pragma unroll
    for (int i = 0; i < 8; i++) {
        int id = i * 256 + tid;
        int n = id >> 4, ch = id & 15;
        cp16(dstBase + xoff(n, ch), src + n * 128 + ch * 8);
    }
    CP_COMMIT();
}

__global__ void prep_kernel(const float* __restrict__ wqkv,
                            const float* __restrict__ wproj) {
    int i = blockIdx.x * blockDim.x + threadIdx.x;
    int m = i >> 14, n = (i >> 7) & 127, k = i & 127;
    float v = (m < 3) ? wqkv[k * 384 + m * 128 + n] : wproj[k * 128 + n];
    g_wh[m][n * 128 + k] = __float2half_rn(v);
}

// D[64,128] = A[64,128] @ B[128,128]; 8 warps, warp tile 32x32.
template <int EPI>   // 0 = scale+fp16 (Q), 1 = fp16 (K/V)
__device__ __forceinline__ void gemm64(uint32_t sb, char* smem,
                                       int aOff, int bOff, int dOff) {
    const int lane = threadIdx.x & 31, wid = threadIdx.x >> 5;
    const int g = lane >> 2, tg = lane & 3;
    const int lg = lane >> 3, lr = lane & 7;
    const int m0 = (wid >> 2) * 32, n0 = (wid & 3) * 32;

    float acc[2][4][4];
#pragma unroll
    for (int mi = 0; mi < 2; mi++)
#pragma unroll
        for (int nb = 0; nb < 4; nb++)
#pragma unroll
            for (int j = 0; j < 4; j++) acc[mi][nb][j] = 0.f;

#pragma unroll
    for (int ks = 0; ks < 8; ks++) {
        uint32_t a[2][4];
#pragma unroll
        for (int mi = 0; mi < 2; mi++)
            ldm4(a[mi], sb + aOff + xoff(m0 + mi * 16 + (lg & 1) * 8 + lr,
                                         ks * 2 + (lg >> 1)));
#pragma unroll
        for (int ni = 0; ni < 2; ni++) {
            uint32_t bf[4];
            ldm4(bf, sb + bOff + xoff(n0 + ni * 16 + (lg >> 1) * 8 + lr,
                                      ks * 2 + (lg & 1)));
#pragma unroll
            for (int mi = 0; mi < 2; mi++) {
                mmaf16(acc[mi][2 * ni], a[mi], bf[0], bf[1]);
                mmaf16(acc[mi][2 * ni + 1], a[mi], bf[2], bf[3]);
            }
        }
    }
#pragma unroll
    for (int mi = 0; mi < 2; mi++)
#pragma unroll
        for (int nb = 0; nb < 4; nb++) {
            int r = m0 + mi * 16 + g;
            int c = n0 + nb * 8 + 2 * tg;
            float v0 = acc[mi][nb][0], v1 = acc[mi][nb][1];
            float v2 = acc[mi][nb][2], v3 = acc[mi][nb][3];
            if (EPI == 0) { v0 *= SCALE_F; v1 *= SCALE_F; v2 *= SCALE_F; v3 *= SCALE_F; }
            *(__half2*)(smem + dOff + xoff(r, c >> 3) + (c & 7) * 2) =
                __floats2half2_rn(v0, v1);
            *(__half2*)(smem + dOff + xoff(r + 8, c >> 3) + (c & 7) * 2) =
                __floats2half2_rn(v2, v3);
        }
}

__global__ void __launch_bounds__(256, 2)
swin_kernel(const float* __restrict__ x,
            const float* __restrict__ bproj,
            float* __restrict__ out) {
    extern __shared__ char smem[];
    const uint32_t sb = s2u(smem);
    const int tid = threadIdx.x, wid = tid >> 5, lane = tid & 31;
    const int g = lane >> 2, tg = lane & 3;
    const int lg = lane >> 3, lr = lane & 7;

    const int p = blockIdx.x;
    const int b = p >> 10;
    const int hs0 = ((p >> 5) & 31) * 8 + 4;
    const int ws0 = (p & 31) * 8 + 4;
    const float* xb = x + (size_t)b * (128 * 256 * 256);

    // ---- stage Wq, Wk; gather shifted X (fp16) -----------------------------
    stageW(sb + W_OFF, g_wh[0], tid);
    stageW(sb + WB_OFF, g_wh[1], tid);
#pragma unroll 4
    for (int i = 0; i < 16; i++) {
        int idx = i * 256 + tid;
        int c2 = idx >> 6, t = idx & 63;
        int h = (hs0 + (t >> 3)) & 255, wv = (ws0 + (t & 7)) & 255;
        const float* src = xb + (size_t)(2 * c2) * 65536 + h * 256 + wv;
        float v0 = __ldg(src), v1 = __ldg(src + 65536);
        *(__half2*)(smem + X_OFF + xoff(t, c2 >> 2) + (c2 & 3) * 4) =
            __floats2half2_rn(v0, v1);
    }
    CP_WAIT0();
    __syncthreads();

    // ---- Q and K back-to-back ----------------------------------------------
    gemm64<0>(sb, smem, X_OFF, W_OFF, Q_OFF);    // Q (scaled)
    gemm64<1>(sb, smem, X_OFF, WB_OFF, K_OFF);   // K
    __syncthreads();
    stageW(sb + W_OFF, g_wh[2], tid);            // Wv
    CP_WAIT0();
    __syncthreads();
    gemm64<1>(sb, smem, X_OFF, W_OFF, WB_OFF);   // V -> WB (Wk dead)
    __syncthreads();                             // V visible; X, W free
    stageW(sb + W_OFF, g_wh[3], tid);            // Wproj (overlaps attention)

    // ---- attention: warp = (head, row-half) ---------------------------------
    const int hd = wid >> 1, hf = wid & 1;
    const int rb = hf * 32;
    const int pO = (wid < 4) ? (X_OFF + wid * 4096) : (Q_OFF + (wid - 4) * 4096);

    uint32_t ph[2][16];
#pragma unroll
    for (int mi = 0; mi < 2; mi++) {
        float s[8][4];
#pragma unroll
        for (int nb = 0; nb < 8; nb++)
#pragma unroll
            for (int j = 0; j < 4; j++) s[nb][j] = 0.f;
#pragma unroll
        for (int ks = 0; ks < 2; ks++) {
            uint32_t a[4];
            ldm4(a, sb + Q_OFF + xoff(rb + mi * 16 + (lg & 1) * 8 + lr,
                                      hd * 4 + ks * 2 + (lg >> 1)));
#pragma unroll
            for (int ni = 0; ni < 4; ni++) {
                uint32_t bf[4];
                ldm4(bf, sb + K_OFF + xoff(ni * 16 + (lg >> 1) * 8 + lr,
                                           hd * 4 + ks * 2 + (lg & 1)));
                mmaf16(s[2 * ni], a, bf[0], bf[1]);
                mmaf16(s[2 * ni + 1], a, bf[2], bf[3]);
            }
        }
#pragma unroll
        for (int h2 = 0; h2 < 2; h2++) {
            float m = -3.0e38f;
#pragma unroll
            for (int nb = 0; nb < 8; nb++)
                m = fmaxf(m, fmaxf(s[nb][2 * h2], s[nb][2 * h2 + 1]));
            m = fmaxf(m, __shfl_xor_sync(0xffffffffu, m, 1));
            m = fmaxf(m, __shfl_xor_sync(0xffffffffu, m, 2));
            float e[16], sum = 0.f;
#pragma unroll
            for (int nb = 0; nb < 8; nb++) {
                float e0 = __expf(s[nb][2 * h2] - m);
                float e1 = __expf(s[nb][2 * h2 + 1] - m);
                e[2 * nb] = e0; e[2 * nb + 1] = e1; sum += e0 + e1;
            }
            sum += __shfl_xor_sync(0xffffffffu, sum, 1);
            sum += __shfl_xor_sync(0xffffffffu, sum, 2);
            float inv = 1.f / sum;
#pragma unroll
            for (int nb = 0; nb < 8; nb++) {
                __half2 hv = __floats2half2_rn(e[2 * nb] * inv, e[2 * nb + 1] * inv);
                ph[mi][h2 * 8 + nb] = *(uint32_t*)&hv;
            }
        }
    }

    __syncthreads();       // all S reads done; safe to overlay P (X/Q) and O (K)

#pragma unroll
    for (int mi = 0; mi < 2; mi++)
#pragma unroll
        for (int h2 = 0; h2 < 2; h2++)
#pragma unroll
            for (int nb = 0; nb < 8; nb++) {
                int r = mi * 16 + h2 * 8 + g;
                int c = nb * 8 + 2 * tg;
                *(uint32_t*)(smem + pO + poff(r, c >> 3) + (c & 7) * 2) =
                    ph[mi][h2 * 8 + nb];
            }
    __syncwarp();

#pragma unroll
    for (int mi = 0; mi < 2; mi++) {
        float o[4][4];
#pragma unroll
        for (int nb = 0; nb < 4; nb++)
#pragma unroll
            for (int j = 0; j < 4; j++) o[nb][j] = 0.f;
#pragma unroll
        for (int tk = 0; tk < 4; tk++) {
            uint32_t a[4];
            ldm4(a, sb + pO + poff(mi * 16 + (lg & 1) * 8 + lr,
                                   tk * 2 + (lg >> 1)));
#pragma unroll
            for (int dp = 0; dp < 2; dp++) {
                uint32_t bf[4];
                ldm4t(bf, sb + WB_OFF + xoff(tk * 16 + (lg & 1) * 8 + lr,
                                             hd * 4 + dp * 2 + (lg >> 1)));
                mmaf16(o[2 * dp], a, bf[0], bf[1]);
                mmaf16(o[2 * dp + 1], a, bf[2], bf[3]);
            }
        }
#pragma unroll
        for (int nb = 0; nb < 4; nb++) {
            int r = rb + mi * 16 + g;
            int c = hd * 32 + nb * 8 + 2 * tg;
            *(__half2*)(smem + K_OFF + xoff(r, c >> 3) + (c & 7) * 2) =
                __floats2half2_rn(o[nb][0], o[nb][1]);
            *(__half2*)(smem + K_OFF + xoff(r + 8, c >> 3) + (c & 7) * 2) =
                __floats2half2_rn(o[nb][2], o[nb][3]);
        }
    }

    CP_WAIT0();            // Wproj staged
    __syncthreads();       // O + Wproj visible

    // ---- proj: Y = O @ WprojT + bias, direct scatter-store -----------------
    {
        const int m0 = (wid >> 2) * 32, n0 = (wid & 3) * 32;
        float acc[2][4][4];
#pragma unroll
        for (int mi = 0; mi < 2; mi++)
#pragma unroll
            for (int nb = 0; nb < 4; nb++)
#pragma unroll
                for (int j = 0; j < 4; j++) acc[mi][nb][j] = 0.f;
#pragma unroll
        for (int ks = 0; ks < 8; ks++) {
            uint32_t a[2][4];
#pragma unroll
            for (int mi = 0; mi < 2; mi++)
                ldm4(a[mi], sb + K_OFF + xoff(m0 + mi * 16 + (lg & 1) * 8 + lr,
                                              ks * 2 + (lg >> 1)));
#pragma unroll
            for (int ni = 0; ni < 2; ni++) {
                uint32_t bf[4];
                ldm4(bf, sb + W_OFF + xoff(n0 + ni * 16 + (lg >> 1) * 8 + lr,
                                           ks * 2 + (lg & 1)));
#pragma unroll
                for (int mi = 0; mi < 2; mi++) {
                    mmaf16(acc[mi][2 * ni], a[mi], bf[0], bf[1]);
                    mmaf16(acc[mi][2 * ni + 1], a[mi], bf[2], bf[3]);
                }
            }
        }
        float* ob = out + (size_t)b * (128 * 256 * 256);
#pragma unroll
        for (int mi = 0; mi < 2; mi++) {
            int t0 = m0 + mi * 16 + g, t1 = t0 + 8;
            float* o0 = ob + ((hs0 + (t0 >> 3)) & 255) * 256 + ((ws0 + (t0 & 7)) & 255);
            float* o1 = ob + ((hs0 + (t1 >> 3)) & 255) * 256 + ((ws0 + (t1 & 7)) & 255);
#pragma unroll
            for (int nb = 0; nb < 4; nb++) {
                int c = n0 + nb * 8 + 2 * tg;
                float b0 = __ldg(bproj + c), b1 = __ldg(bproj + c + 1);
                o0[(size_t)c * 65536] = acc[mi][nb][0] + b0;
                o0[(size_t)(c + 1) * 65536] = acc[mi][nb][1] + b1;
                o1[(size_t)c * 65536] = acc[mi][nb][2] + b0;
                o1[(size_t)(c + 1) * 65536] = acc[mi][nb][3] + b1;
            }
        }
    }
}

extern "C" void kernel_launch(void* const* d_in, const int* in_sizes, int n_in,
                              void* d_out, int out_size) {
    const float* x     = (const float*)d_in[0];
    const float* wqkv  = (const float*)d_in[1];
    const float* wproj = (const float*)d_in[2];
    const float* bproj = (const float*)d_in[3];
    float* out = (float*)d_out;

    prep_kernel<<<256, 256>>>(wqkv, wproj);

    cudaFuncSetAttribute(swin_kernel,
                         cudaFuncAttributeMaxDynamicSharedMemorySize, SMEM_TOTAL);
    swin_kernel<<<8192, 256, SMEM_TOTAL>>>(x, bproj, out);
}